// round 3
// baseline (speedup 1.0000x reference)
#include <cuda_runtime.h>
#include <cuda_bf16.h>
#include <cstdint>
#include <math.h>

#define H 256
#define C 512
#define V 32000
#define NB 64
#define T 512

#define CLU 8      // CTAs per cluster
#define CPC 4      // chains per cluster
#define CSL 64     // c' columns per CTA

// ------------------------- static device scratch -------------------------
__device__ float g_startP[C];                  // start probs
__device__ float g_P[C * C];                   // transition (logits, then probs in place)
__device__ float g_fe[C * H];                  // terminal MLP output
__device__ float g_L[(size_t)C * V];           // emission logits
__device__ float g_rowmax[C];
__device__ float g_rowinv[C];
__device__ float g_emisT[(size_t)V * C];       // emission probs, [V][C]
__device__ float g_logZ[NB];

// ------------------------------ helpers ------------------------------
__device__ __forceinline__ float warpMax(float v) {
#pragma unroll
    for (int o = 16; o > 0; o >>= 1) v = fmaxf(v, __shfl_xor_sync(0xffffffffu, v, o));
    return v;
}
__device__ __forceinline__ float warpSum(float v) {
#pragma unroll
    for (int o = 16; o > 0; o >>= 1) v += __shfl_xor_sync(0xffffffffu, v, o);
    return v;
}
// block of 256 threads
__device__ __forceinline__ float blockMax256(float v, float* sred) {
    v = warpMax(v);
    int w = threadIdx.x >> 5, ln = threadIdx.x & 31;
    if (ln == 0) sred[w] = v;
    __syncthreads();
    if (w == 0) {
        float x = (ln < 8) ? sred[ln] : -3.4e38f;
        x = warpMax(x);
        if (ln == 0) sred[0] = x;
    }
    __syncthreads();
    float r = sred[0];
    __syncthreads();
    return r;
}
__device__ __forceinline__ float blockSum256(float v, float* sred) {
    v = warpSum(v);
    int w = threadIdx.x >> 5, ln = threadIdx.x & 31;
    if (ln == 0) sred[w] = v;
    __syncthreads();
    if (w == 0) {
        float x = (ln < 8) ? sred[ln] : 0.f;
        x = warpSum(x);
        if (ln == 0) sred[0] = x;
    }
    __syncthreads();
    float r = sred[0];
    __syncthreads();
    return r;
}
__device__ __forceinline__ unsigned smem_u32(const void* p) {
    return (unsigned)__cvta_generic_to_shared(p);
}

// ------------------------------ start vector ------------------------------
__global__ __launch_bounds__(256) void start_kernel(
    const float* __restrict__ se, const float* __restrict__ sw,
    const float* __restrict__ sb, const float* __restrict__ rw,
    const float* __restrict__ rb, const float* __restrict__ nse)
{
    __shared__ float x[H];
    __shared__ float h[H];
    __shared__ float sred[32];
    int tid = threadIdx.x;

    x[tid] = se[tid];
    __syncthreads();
    // fx = se @ sw + sb
    float a = sb[tid];
#pragma unroll 4
    for (int k = 0; k < H; ++k) a = fmaf(x[k], sw[k * H + tid], a);
    __syncthreads();
    x[tid] = a;
    __syncthreads();
    // two ResLayers
    for (int l = 0; l < 2; ++l) {
        const float* w1 = rw + (size_t)(l * 2 + 0) * H * H;
        const float* b1 = rb + (l * 2 + 0) * H;
        const float* w2 = rw + (size_t)(l * 2 + 1) * H * H;
        const float* b2 = rb + (l * 2 + 1) * H;
        float a1 = b1[tid];
#pragma unroll 4
        for (int k = 0; k < H; ++k) a1 = fmaf(x[k], w1[k * H + tid], a1);
        h[tid] = fmaxf(a1, 0.f);
        __syncthreads();
        float a2 = b2[tid];
#pragma unroll 4
        for (int k = 0; k < H; ++k) a2 = fmaf(h[k], w2[k * H + tid], a2);
        __syncthreads();
        x[tid] += fmaxf(a2, 0.f);
        __syncthreads();
    }
    // logits over C=512 and softmax
    float l0 = 0.f, l1 = 0.f;
    const float* r0 = nse + (size_t)tid * H;
    const float* r1 = nse + (size_t)(tid + 256) * H;
#pragma unroll 4
    for (int k = 0; k < H; ++k) {
        float xv = x[k];
        l0 = fmaf(xv, r0[k], l0);
        l1 = fmaf(xv, r1[k], l1);
    }
    float m = blockMax256(fmaxf(l0, l1), sred);
    float e0 = expf(l0 - m), e1 = expf(l1 - m);
    float s = blockSum256(e0 + e1, sred);
    float inv = 1.f / s;
    g_startP[tid] = e0 * inv;
    g_startP[tid + 256] = e1 * inv;
}

// ------------------------------ terminal MLP ------------------------------
__global__ __launch_bounds__(256) void term_mlp_kernel(
    const float* __restrict__ pre, const float* __restrict__ rw,
    const float* __restrict__ rb)
{
    __shared__ float xs[8][H];
    __shared__ float hs[8][H];
    int r0 = blockIdx.x * 8;
    int tid = threadIdx.x;
    for (int i = tid; i < 8 * H; i += 256)
        xs[i >> 8][i & 255] = pre[(size_t)(r0 + (i >> 8)) * H + (i & 255)];
    __syncthreads();
    for (int l = 0; l < 2; ++l) {
        const float* w1 = rw + (size_t)(l * 2 + 0) * H * H;
        const float* b1 = rb + (l * 2 + 0) * H;
        const float* w2 = rw + (size_t)(l * 2 + 1) * H * H;
        const float* b2 = rb + (l * 2 + 1) * H;
        float acc[8];
#pragma unroll
        for (int r = 0; r < 8; ++r) acc[r] = b1[tid];
#pragma unroll 2
        for (int k = 0; k < H; ++k) {
            float w = w1[k * H + tid];
#pragma unroll
            for (int r = 0; r < 8; ++r) acc[r] = fmaf(xs[r][k], w, acc[r]);
        }
#pragma unroll
        for (int r = 0; r < 8; ++r) hs[r][tid] = fmaxf(acc[r], 0.f);
        __syncthreads();
#pragma unroll
        for (int r = 0; r < 8; ++r) acc[r] = b2[tid];
#pragma unroll 2
        for (int k = 0; k < H; ++k) {
            float w = w2[k * H + tid];
#pragma unroll
            for (int r = 0; r < 8; ++r) acc[r] = fmaf(hs[r][k], w, acc[r]);
        }
        __syncthreads();
#pragma unroll
        for (int r = 0; r < 8; ++r) xs[r][tid] += fmaxf(acc[r], 0.f);
        __syncthreads();
    }
    for (int i = tid; i < 8 * H; i += 256)
        g_fe[(size_t)(r0 + (i >> 8)) * H + (i & 255)] = xs[i >> 8][i & 255];
}

// --------------------- generic NT GEMM: out[m][n] = A[m][:] . B[n][:] ------
// dest: 0 -> g_P (transition logits), 1 -> g_L (emission logits)
#define GBM 64
#define GBN 128
#define GBK 32
__global__ __launch_bounds__(256) void gemm_nt(
    const float* __restrict__ A, const float* __restrict__ B,
    int dest, int Ncols)
{
    __shared__ float As[GBK][GBM + 1];
    __shared__ float Bs[GBK][GBN + 4];
    float* Cout = dest ? g_L : g_P;
    int bm = blockIdx.y * GBM;
    int bn = blockIdx.x * GBN;
    int tid = threadIdx.x;
    int tm = (tid >> 4) * 4;
    int tn = (tid & 15) * 8;
    float acc[4][8];
#pragma unroll
    for (int i = 0; i < 4; ++i)
#pragma unroll
        for (int j = 0; j < 8; ++j) acc[i][j] = 0.f;

    for (int k0 = 0; k0 < H; k0 += GBK) {
#pragma unroll
        for (int q = 0; q < 2; ++q) {
            int i = tid + q * 256;
            int m = i >> 3, f = i & 7;
            float4 v = *(const float4*)(A + (size_t)(bm + m) * H + k0 + f * 4);
            As[f * 4 + 0][m] = v.x; As[f * 4 + 1][m] = v.y;
            As[f * 4 + 2][m] = v.z; As[f * 4 + 3][m] = v.w;
        }
#pragma unroll
        for (int q = 0; q < 4; ++q) {
            int i = tid + q * 256;
            int n = i >> 3, f = i & 7;
            float4 v = *(const float4*)(B + (size_t)(bn + n) * H + k0 + f * 4);
            Bs[f * 4 + 0][n] = v.x; Bs[f * 4 + 1][n] = v.y;
            Bs[f * 4 + 2][n] = v.z; Bs[f * 4 + 3][n] = v.w;
        }
        __syncthreads();
#pragma unroll
        for (int kk = 0; kk < GBK; ++kk) {
            float ra[4], rb[8];
#pragma unroll
            for (int i = 0; i < 4; ++i) ra[i] = As[kk][tm + i];
#pragma unroll
            for (int j = 0; j < 8; ++j) rb[j] = Bs[kk][tn + j];
#pragma unroll
            for (int i = 0; i < 4; ++i)
#pragma unroll
                for (int j = 0; j < 8; ++j) acc[i][j] = fmaf(ra[i], rb[j], acc[i][j]);
        }
        __syncthreads();
    }
#pragma unroll
    for (int i = 0; i < 4; ++i) {
#pragma unroll
        for (int j = 0; j < 8; j += 4) {
            float4 v = make_float4(acc[i][j], acc[i][j + 1], acc[i][j + 2], acc[i][j + 3]);
            *(float4*)(Cout + (size_t)(bm + tm + i) * Ncols + bn + tn + j) = v;
        }
    }
}

// --------------------- transition row softmax (in place on g_P) -----------
__global__ __launch_bounds__(256) void p_softmax_kernel()
{
    __shared__ float sred[32];
    int c = blockIdx.x;
    int tid = threadIdx.x;
    float* row = g_P + (size_t)c * C;
    float v0 = row[tid], v1 = row[tid + 256];
    float m = blockMax256(fmaxf(v0, v1), sred);
    float e0 = expf(v0 - m), e1 = expf(v1 - m);
    float s = blockSum256(e0 + e1, sred);
    float inv = 1.f / s;
    row[tid] = e0 * inv;
    row[tid + 256] = e1 * inv;
}

// --------------------- emission row stats (max, 1/sumexp) -----------------
__global__ __launch_bounds__(256) void rowstats_kernel()
{
    __shared__ float sred[32];
    int c = blockIdx.x;
    int tid = threadIdx.x;
    const float4* row = (const float4*)(g_L + (size_t)c * V);
    float mx = -3.4e38f;
    for (int i = tid; i < V / 4; i += 256) {
        float4 v = row[i];
        mx = fmaxf(mx, fmaxf(fmaxf(v.x, v.y), fmaxf(v.z, v.w)));
    }
    float m = blockMax256(mx, sred);
    float s = 0.f;
    for (int i = tid; i < V / 4; i += 256) {
        float4 v = row[i];
        s += expf(v.x - m) + expf(v.y - m) + expf(v.z - m) + expf(v.w - m);
    }
    float tot = blockSum256(s, sred);
    if (tid == 0) {
        g_rowmax[c] = m;
        g_rowinv[c] = 1.f / tot;
    }
}

// --------------------- normalize + transpose to [V][C] --------------------
__global__ __launch_bounds__(256) void norm_transpose_kernel()
{
    __shared__ float tile[32][33];
    int v0 = blockIdx.x * 32;
    int c0 = blockIdx.y * 32;
    int tid = threadIdx.x;
    int col = tid & 31;
    int rr = tid >> 5;
#pragma unroll
    for (int q = 0; q < 4; ++q) {
        int r = rr + q * 8;  // local c
        float l = g_L[(size_t)(c0 + r) * V + v0 + col];
        tile[r][col] = expf(l - g_rowmax[c0 + r]) * g_rowinv[c0 + r];
    }
    __syncthreads();
#pragma unroll
    for (int q = 0; q < 4; ++q) {
        int r = rr + q * 8;  // local v
        g_emisT[(size_t)(v0 + r) * C + c0 + col] = tile[col][r];
    }
}

// ------------------------------ HMM scan ------------------------------
__global__ void __cluster_dims__(CLU, 1, 1) __launch_bounds__(256, 1)
scan_kernel(const int* __restrict__ text)
{
    __shared__ float A[CPC][C];          // current scaled alpha (replicated per CTA)
    __shared__ float Bf[2][CPC][C];      // double-buffered all-gather target
    __shared__ float part[4][CPC][CSL];  // K-group partials
    __shared__ float red[CPC][CSL];
    __shared__ float m_s[CPC];
    __shared__ float ls_s[CPC];
    __shared__ int toks[2][CPC];

    const int tid = threadIdx.x;
    const int rank = blockIdx.x & (CLU - 1);
    const int chain0 = (blockIdx.x >> 3) * CPC;
    const int c0 = rank * CSL;
    const int g = tid >> 6;      // K-group 0..3
    const int cl = tid & 63;     // local c'
    const int n4 = g;            // chain index in scale phases
    const int nn = tid >> 5;     // for 128-thread phases
    const int jj = tid & 31;

    // P slice into registers: Preg[k] = P[g*128+k][c0+cl]  (time-invariant)
    float Preg[128];
#pragma unroll
    for (int k = 0; k < 128; ++k)
        Preg[k] = g_P[(size_t)(g * 128 + k) * C + c0 + cl];

    if (tid < CPC) {
        toks[0][tid] = text[(chain0 + tid) * T + 0];
        toks[1][tid] = text[(chain0 + tid) * T + 1];
        ls_s[tid] = 0.f;
    }
    __syncthreads();

    // alpha0 = startP * B[:, x0] (every CTA computes the full replicated copy)
    for (int i = tid; i < CPC * C; i += 256) {
        int n = i >> 9, c = i & (C - 1);
        A[n][c] = g_startP[c] * g_emisT[(size_t)toks[0][n] * C + c];
    }
    __syncthreads();
    // init rescale of A in place
    {
        float mx = 0.f;
#pragma unroll
        for (int j = 0; j < 8; ++j) mx = fmaxf(mx, A[n4][cl + 64 * j]);
        red[n4][cl] = mx;
        __syncthreads();
        if (tid < 128) {
            float v = fmaxf(red[nn][jj], red[nn][jj + 32]);
            v = warpMax(v);
            if (jj == 0) m_s[nn] = v;
        }
        __syncthreads();
        float inv = 1.f / m_s[n4];
#pragma unroll
        for (int j = 0; j < 8; ++j) A[n4][cl + 64 * j] *= inv;
        if (tid < CPC) ls_s[tid] += logf(m_s[tid]);
        __syncthreads();
    }

    const unsigned bfAddr[2] = { smem_u32(&Bf[0][0][0]), smem_u32(&Bf[1][0][0]) };

    for (int t = 1; t < T; ++t) {
        const int pb = t & 1;
        // prefetch emission pair for this step (token loaded last step)
        float ev0 = 0.f, ev1 = 0.f;
        if (tid < 128) {
            const float2 e2 = *(const float2*)(g_emisT +
                (size_t)toks[pb][nn] * C + c0 + 2 * jj);
            ev0 = e2.x; ev1 = e2.y;
        }
        // prefetch next token
        if (tid >= 252 && t + 1 < T)
            toks[(t + 1) & 1][tid - 252] = text[(chain0 + tid - 252) * T + (t + 1)];

        // partial dot over this thread's K-chunk, all 4 chains
        float a0 = 0.f, a1 = 0.f, a2 = 0.f, a3 = 0.f;
        {
            const float4* r0 = (const float4*)&A[0][g * 128];
            const float4* r1 = (const float4*)&A[1][g * 128];
            const float4* r2 = (const float4*)&A[2][g * 128];
            const float4* r3 = (const float4*)&A[3][g * 128];
#pragma unroll
            for (int k4 = 0; k4 < 32; ++k4) {
                const float4 v0 = r0[k4], v1 = r1[k4], v2 = r2[k4], v3 = r3[k4];
                const float p0 = Preg[4 * k4 + 0], p1 = Preg[4 * k4 + 1];
                const float p2 = Preg[4 * k4 + 2], p3 = Preg[4 * k4 + 3];
                a0 = fmaf(v0.x, p0, a0); a0 = fmaf(v0.y, p1, a0);
                a0 = fmaf(v0.z, p2, a0); a0 = fmaf(v0.w, p3, a0);
                a1 = fmaf(v1.x, p0, a1); a1 = fmaf(v1.y, p1, a1);
                a1 = fmaf(v1.z, p2, a1); a1 = fmaf(v1.w, p3, a1);
                a2 = fmaf(v2.x, p0, a2); a2 = fmaf(v2.y, p1, a2);
                a2 = fmaf(v2.z, p2, a2); a2 = fmaf(v2.w, p3, a2);
                a3 = fmaf(v3.x, p0, a3); a3 = fmaf(v3.y, p1, a3);
                a3 = fmaf(v3.z, p2, a3); a3 = fmaf(v3.w, p3, a3);
            }
        }
        part[g][0][cl] = a0;
        part[g][1][cl] = a1;
        part[g][2][cl] = a2;
        part[g][3][cl] = a3;
        __syncthreads();

        // reduce K-groups, apply emission, broadcast slice to all 8 CTAs
        if (tid < 128) {
            int cc = 2 * jj;
            float s0 = ((part[0][nn][cc] + part[1][nn][cc]) +
                        (part[2][nn][cc] + part[3][nn][cc])) * ev0;
            float s1 = ((part[0][nn][cc + 1] + part[1][nn][cc + 1]) +
                        (part[2][nn][cc + 1] + part[3][nn][cc + 1])) * ev1;
            unsigned long long pk = (unsigned long long)__float_as_uint(s0) |
                ((unsigned long long)__float_as_uint(s1) << 32);
            unsigned base = bfAddr[pb] + (unsigned)((nn * C + c0 + cc) * 4);
#pragma unroll
            for (int r = 0; r < CLU; ++r) {
                unsigned ra;
                asm volatile("mapa.shared::cluster.u32 %0, %1, %2;"
                             : "=r"(ra) : "r"(base), "r"(r));
                asm volatile("st.shared::cluster.b64 [%0], %1;"
                             :: "r"(ra), "l"(pk) : "memory");
            }
        }
        asm volatile("barrier.cluster.arrive.aligned;" ::: "memory");
        asm volatile("barrier.cluster.wait.aligned;" ::: "memory");

        // rescale Bf[pb] -> A, accumulate log scale
        float mx = 0.f;
#pragma unroll
        for (int j = 0; j < 8; ++j) mx = fmaxf(mx, Bf[pb][n4][cl + 64 * j]);
        red[n4][cl] = mx;
        __syncthreads();
        if (tid < 128) {
            float v = fmaxf(red[nn][jj], red[nn][jj + 32]);
            v = warpMax(v);
            if (jj == 0) m_s[nn] = v;
        }
        __syncthreads();
        float inv = 1.f / m_s[n4];
#pragma unroll
        for (int j = 0; j < 8; ++j) A[n4][cl + 64 * j] = Bf[pb][n4][cl + 64 * j] * inv;
        if (tid < CPC) ls_s[tid] += logf(m_s[tid]);
        __syncthreads();
    }

    // final: logZ[n] = ls[n] + log(sum_c A[n][c])
    {
        float sm = 0.f;
#pragma unroll
        for (int j = 0; j < 8; ++j) sm += A[n4][cl + 64 * j];
        red[n4][cl] = sm;
        __syncthreads();
        if (tid < 128) {
            float v = red[nn][jj] + red[nn][jj + 32];
            v = warpSum(v);
            if (jj == 0 && rank == 0)
                g_logZ[chain0 + nn] = ls_s[nn] + logf(v);
        }
    }
}

// ------------------------------ final reduction ------------------------------
__global__ void final_sum_kernel(float* __restrict__ out)
{
    __shared__ float s[64];
    int tid = threadIdx.x;
    s[tid] = g_logZ[tid];
    __syncthreads();
#pragma unroll
    for (int o = 32; o > 0; o >>= 1) {
        if (tid < o) s[tid] += s[tid + o];
        __syncthreads();
    }
    if (tid == 0) out[0] = s[0];
}

// ------------------------------ launch ------------------------------
extern "C" void kernel_launch(void* const* d_in, const int* in_sizes, int n_in,
                              void* d_out, int out_size)
{
    const int*   text  = (const int*)  d_in[0];
    const float* se    = (const float*)d_in[1];
    const float* sw    = (const float*)d_in[2];
    const float* sb    = (const float*)d_in[3];
    const float* srw   = (const float*)d_in[4];
    const float* srb   = (const float*)d_in[5];
    const float* state = (const float*)d_in[6];
    const float* nse   = (const float*)d_in[7];
    const float* pre   = (const float*)d_in[8];
    const float* trw   = (const float*)d_in[9];
    const float* trb   = (const float*)d_in[10];
    const float* term  = (const float*)d_in[11];
    float* out = (float*)d_out;

    // start distribution
    start_kernel<<<1, 256>>>(se, sw, sb, srw, srb, nse);
    // transition logits -> probs
    gemm_nt<<<dim3(C / GBN, C / GBM), 256>>>(state, nse, /*dest=*/0, C);
    p_softmax_kernel<<<C, 256>>>();
    // terminal MLP -> fe
    term_mlp_kernel<<<C / 8, 256>>>(pre, trw, trb);
    // emission logits -> probs transposed
    gemm_nt<<<dim3(V / GBN, C / GBM), 256>>>(g_fe, term, /*dest=*/1, V);
    rowstats_kernel<<<C, 256>>>();
    norm_transpose_kernel<<<dim3(V / 32, C / 32), 256>>>();
    // forward scan (16 clusters x 8 CTAs)
    scan_kernel<<<(NB / CPC) * CLU, 256>>>(text);
    // evidence
    final_sum_kernel<<<1, 64>>>(out);
}

// round 4
// speedup vs baseline: 1.2248x; 1.2248x over previous
#include <cuda_runtime.h>
#include <cuda_bf16.h>
#include <cstdint>
#include <math.h>

#define H 256
#define C 512
#define V 32000
#define NB 64
#define T 512

#define CLU 8      // CTAs per cluster
#define CPC 4      // chains per cluster
#define CSL 64     // c' columns per CTA

// ------------------------- static device scratch -------------------------
__device__ float g_startP[C];
__device__ float g_P[C * C];
__device__ float g_fe[C * H];
__device__ float g_L[(size_t)C * V];
__device__ float g_rowmax[C];
__device__ float g_rowinv[C];
__device__ float g_emisT[(size_t)V * C];
__device__ float g_logZ[NB];

// ------------------------------ helpers ------------------------------
__device__ __forceinline__ unsigned long long pk2(float lo, float hi) {
    unsigned long long r;
    asm("mov.b64 %0, {%1, %2};" : "=l"(r) : "f"(lo), "f"(hi));
    return r;
}
__device__ __forceinline__ void upk2(unsigned long long v, float& lo, float& hi) {
    asm("mov.b64 {%0, %1}, %2;" : "=f"(lo), "=f"(hi) : "l"(v));
}
__device__ __forceinline__ unsigned long long fma2(
    unsigned long long a, unsigned long long b, unsigned long long c) {
    unsigned long long d;
    asm("fma.rn.f32x2 %0, %1, %2, %3;" : "=l"(d) : "l"(a), "l"(b), "l"(c));
    return d;
}
__device__ __forceinline__ float warpMax(float v) {
#pragma unroll
    for (int o = 16; o > 0; o >>= 1) v = fmaxf(v, __shfl_xor_sync(0xffffffffu, v, o));
    return v;
}
__device__ __forceinline__ float warpSum(float v) {
#pragma unroll
    for (int o = 16; o > 0; o >>= 1) v += __shfl_xor_sync(0xffffffffu, v, o);
    return v;
}
__device__ __forceinline__ float blockMax256(float v, float* sred) {
    v = warpMax(v);
    int w = threadIdx.x >> 5, ln = threadIdx.x & 31;
    if (ln == 0) sred[w] = v;
    __syncthreads();
    if (w == 0) {
        float x = (ln < 8) ? sred[ln] : -3.4e38f;
        x = warpMax(x);
        if (ln == 0) sred[0] = x;
    }
    __syncthreads();
    float r = sred[0];
    __syncthreads();
    return r;
}
__device__ __forceinline__ float blockSum256(float v, float* sred) {
    v = warpSum(v);
    int w = threadIdx.x >> 5, ln = threadIdx.x & 31;
    if (ln == 0) sred[w] = v;
    __syncthreads();
    if (w == 0) {
        float x = (ln < 8) ? sred[ln] : 0.f;
        x = warpSum(x);
        if (ln == 0) sred[0] = x;
    }
    __syncthreads();
    float r = sred[0];
    __syncthreads();
    return r;
}
__device__ __forceinline__ unsigned smem_u32(const void* p) {
    return (unsigned)__cvta_generic_to_shared(p);
}

// ------------------------------ start vector ------------------------------
__global__ __launch_bounds__(256) void start_kernel(
    const float* __restrict__ se, const float* __restrict__ sw,
    const float* __restrict__ sb, const float* __restrict__ rw,
    const float* __restrict__ rb, const float* __restrict__ nse)
{
    __shared__ __align__(16) float x[H];
    __shared__ __align__(16) float h[H];
    __shared__ float sred[32];
    int tid = threadIdx.x;

    x[tid] = se[tid];
    __syncthreads();
    // fx = se @ sw + sb, batched loads (MLP=8)
    {
        float a = sb[tid];
        for (int k0 = 0; k0 < H; k0 += 8) {
            float w[8];
#pragma unroll
            for (int u = 0; u < 8; ++u) w[u] = sw[(k0 + u) * H + tid];
#pragma unroll
            for (int u = 0; u < 8; ++u) a = fmaf(x[k0 + u], w[u], a);
        }
        __syncthreads();
        x[tid] = a;
        __syncthreads();
    }
    for (int l = 0; l < 2; ++l) {
        const float* w1 = rw + (size_t)(l * 2 + 0) * H * H;
        const float* b1 = rb + (l * 2 + 0) * H;
        const float* w2 = rw + (size_t)(l * 2 + 1) * H * H;
        const float* b2 = rb + (l * 2 + 1) * H;
        float a1 = b1[tid];
        for (int k0 = 0; k0 < H; k0 += 8) {
            float w[8];
#pragma unroll
            for (int u = 0; u < 8; ++u) w[u] = w1[(k0 + u) * H + tid];
#pragma unroll
            for (int u = 0; u < 8; ++u) a1 = fmaf(x[k0 + u], w[u], a1);
        }
        h[tid] = fmaxf(a1, 0.f);
        __syncthreads();
        float a2 = b2[tid];
        for (int k0 = 0; k0 < H; k0 += 8) {
            float w[8];
#pragma unroll
            for (int u = 0; u < 8; ++u) w[u] = w2[(k0 + u) * H + tid];
#pragma unroll
            for (int u = 0; u < 8; ++u) a2 = fmaf(h[k0 + u], w[u], a2);
        }
        __syncthreads();
        x[tid] += fmaxf(a2, 0.f);
        __syncthreads();
    }
    // logits over C=512, float4 streaming of nse rows
    float l0 = 0.f, l1 = 0.f;
    const float4* r0 = (const float4*)(nse + (size_t)tid * H);
    const float4* r1 = (const float4*)(nse + (size_t)(tid + 256) * H);
    const float4* xv4 = (const float4*)x;
#pragma unroll 4
    for (int k4 = 0; k4 < H / 4; ++k4) {
        float4 xa = xv4[k4];
        float4 a = r0[k4], b = r1[k4];
        l0 = fmaf(xa.x, a.x, l0); l0 = fmaf(xa.y, a.y, l0);
        l0 = fmaf(xa.z, a.z, l0); l0 = fmaf(xa.w, a.w, l0);
        l1 = fmaf(xa.x, b.x, l1); l1 = fmaf(xa.y, b.y, l1);
        l1 = fmaf(xa.z, b.z, l1); l1 = fmaf(xa.w, b.w, l1);
    }
    float m = blockMax256(fmaxf(l0, l1), sred);
    float e0 = expf(l0 - m), e1 = expf(l1 - m);
    float s = blockSum256(e0 + e1, sred);
    float inv = 1.f / s;
    g_startP[tid] = e0 * inv;
    g_startP[tid + 256] = e1 * inv;
}

// ------------------------------ terminal MLP ------------------------------
#define TROWS 4
__global__ __launch_bounds__(256) void term_mlp_kernel(
    const float* __restrict__ pre, const float* __restrict__ rw,
    const float* __restrict__ rb)
{
    __shared__ __align__(16) float xs[TROWS][H];
    __shared__ __align__(16) float hs[TROWS][H];
    int r0 = blockIdx.x * TROWS;
    int tid = threadIdx.x;
    for (int i = tid; i < TROWS * H; i += 256)
        xs[i >> 8][i & 255] = pre[(size_t)(r0 + (i >> 8)) * H + (i & 255)];
    __syncthreads();
    for (int l = 0; l < 2; ++l) {
        const float* w1 = rw + (size_t)(l * 2 + 0) * H * H;
        const float* b1 = rb + (l * 2 + 0) * H;
        const float* w2 = rw + (size_t)(l * 2 + 1) * H * H;
        const float* b2 = rb + (l * 2 + 1) * H;
        float acc[TROWS];
#pragma unroll
        for (int r = 0; r < TROWS; ++r) acc[r] = b1[tid];
        for (int k0 = 0; k0 < H; k0 += 8) {
            float w[8];
#pragma unroll
            for (int u = 0; u < 8; ++u) w[u] = w1[(k0 + u) * H + tid];
#pragma unroll
            for (int u = 0; u < 8; ++u)
#pragma unroll
                for (int r = 0; r < TROWS; ++r)
                    acc[r] = fmaf(xs[r][k0 + u], w[u], acc[r]);
        }
#pragma unroll
        for (int r = 0; r < TROWS; ++r) hs[r][tid] = fmaxf(acc[r], 0.f);
        __syncthreads();
#pragma unroll
        for (int r = 0; r < TROWS; ++r) acc[r] = b2[tid];
        for (int k0 = 0; k0 < H; k0 += 8) {
            float w[8];
#pragma unroll
            for (int u = 0; u < 8; ++u) w[u] = w2[(k0 + u) * H + tid];
#pragma unroll
            for (int u = 0; u < 8; ++u)
#pragma unroll
                for (int r = 0; r < TROWS; ++r)
                    acc[r] = fmaf(hs[r][k0 + u], w[u], acc[r]);
        }
        __syncthreads();
#pragma unroll
        for (int r = 0; r < TROWS; ++r) xs[r][tid] += fmaxf(acc[r], 0.f);
        __syncthreads();
    }
    for (int i = tid; i < TROWS * H; i += 256)
        g_fe[(size_t)(r0 + (i >> 8)) * H + (i & 255)] = xs[i >> 8][i & 255];
}

// --------------------- NT GEMM with packed f32x2: out[m][n] = A[m].B[n] ----
#define GBM 64
#define GBN 128
#define GBK 32
__global__ __launch_bounds__(256) void gemm_nt(
    const float* __restrict__ A, const float* __restrict__ B,
    int dest, int Ncols)
{
    __shared__ __align__(16) float As[GBK][GBM + 1];
    __shared__ __align__(16) float Bs[GBK][GBN + 4];
    float* Cout = dest ? g_L : g_P;
    int bm = blockIdx.y * GBM;
    int bn = blockIdx.x * GBN;
    int tid = threadIdx.x;
    int tm = (tid >> 4) * 4;
    int tn = (tid & 15) * 8;
    unsigned long long acc2[4][4];
#pragma unroll
    for (int i = 0; i < 4; ++i)
#pragma unroll
        for (int j = 0; j < 4; ++j) acc2[i][j] = 0ull;

    for (int k0 = 0; k0 < H; k0 += GBK) {
#pragma unroll
        for (int q = 0; q < 2; ++q) {
            int i = tid + q * 256;
            int m = i >> 3, f = i & 7;
            float4 v = *(const float4*)(A + (size_t)(bm + m) * H + k0 + f * 4);
            As[f * 4 + 0][m] = v.x; As[f * 4 + 1][m] = v.y;
            As[f * 4 + 2][m] = v.z; As[f * 4 + 3][m] = v.w;
        }
#pragma unroll
        for (int q = 0; q < 4; ++q) {
            int i = tid + q * 256;
            int n = i >> 3, f = i & 7;
            float4 v = *(const float4*)(B + (size_t)(bn + n) * H + k0 + f * 4);
            Bs[f * 4 + 0][n] = v.x; Bs[f * 4 + 1][n] = v.y;
            Bs[f * 4 + 2][n] = v.z; Bs[f * 4 + 3][n] = v.w;
        }
        __syncthreads();
#pragma unroll
        for (int kk = 0; kk < GBK; ++kk) {
            unsigned long long ra2[4], rb2[4];
#pragma unroll
            for (int i = 0; i < 4; ++i) {
                float a = As[kk][tm + i];
                ra2[i] = pk2(a, a);
            }
            const unsigned long long* bp = (const unsigned long long*)&Bs[kk][tn];
#pragma unroll
            for (int j = 0; j < 4; ++j) rb2[j] = bp[j];
#pragma unroll
            for (int i = 0; i < 4; ++i)
#pragma unroll
                for (int j = 0; j < 4; ++j)
                    acc2[i][j] = fma2(ra2[i], rb2[j], acc2[i][j]);
        }
        __syncthreads();
    }
#pragma unroll
    for (int i = 0; i < 4; ++i) {
        float c[8];
#pragma unroll
        for (int j = 0; j < 4; ++j) upk2(acc2[i][j], c[2 * j], c[2 * j + 1]);
        *(float4*)(Cout + (size_t)(bm + tm + i) * Ncols + bn + tn) =
            make_float4(c[0], c[1], c[2], c[3]);
        *(float4*)(Cout + (size_t)(bm + tm + i) * Ncols + bn + tn + 4) =
            make_float4(c[4], c[5], c[6], c[7]);
    }
}

// --------------------- transition row softmax ------------------------------
__global__ __launch_bounds__(256) void p_softmax_kernel()
{
    __shared__ float sred[32];
    int c = blockIdx.x;
    int tid = threadIdx.x;
    float* row = g_P + (size_t)c * C;
    float v0 = row[tid], v1 = row[tid + 256];
    float m = blockMax256(fmaxf(v0, v1), sred);
    float e0 = expf(v0 - m), e1 = expf(v1 - m);
    float s = blockSum256(e0 + e1, sred);
    float inv = 1.f / s;
    row[tid] = e0 * inv;
    row[tid + 256] = e1 * inv;
}

// --------------------- emission row stats ----------------------------------
__global__ __launch_bounds__(256) void rowstats_kernel()
{
    __shared__ float sred[32];
    int c = blockIdx.x;
    int tid = threadIdx.x;
    const float4* row = (const float4*)(g_L + (size_t)c * V);
    float mx = -3.4e38f;
    for (int i = tid; i < V / 4; i += 256) {
        float4 v = row[i];
        mx = fmaxf(mx, fmaxf(fmaxf(v.x, v.y), fmaxf(v.z, v.w)));
    }
    float m = blockMax256(mx, sred);
    float s = 0.f;
    for (int i = tid; i < V / 4; i += 256) {
        float4 v = row[i];
        s += expf(v.x - m) + expf(v.y - m) + expf(v.z - m) + expf(v.w - m);
    }
    float tot = blockSum256(s, sred);
    if (tid == 0) {
        g_rowmax[c] = m;
        g_rowinv[c] = 1.f / tot;
    }
}

// --------------------- normalize + transpose to [V][C] ---------------------
__global__ __launch_bounds__(256) void norm_transpose_kernel()
{
    __shared__ float tile[32][33];
    int v0 = blockIdx.x * 32;
    int c0 = blockIdx.y * 32;
    int tid = threadIdx.x;
    int col = tid & 31;
    int rr = tid >> 5;
#pragma unroll
    for (int q = 0; q < 4; ++q) {
        int r = rr + q * 8;
        float l = g_L[(size_t)(c0 + r) * V + v0 + col];
        tile[r][col] = expf(l - g_rowmax[c0 + r]) * g_rowinv[c0 + r];
    }
    __syncthreads();
#pragma unroll
    for (int q = 0; q < 4; ++q) {
        int r = rr + q * 8;
        g_emisT[(size_t)(v0 + r) * C + c0 + col] = tile[col][r];
    }
}

// ------------------------------ HMM scan ------------------------------
__global__ void __cluster_dims__(CLU, 1, 1) __launch_bounds__(256, 1)
scan_kernel(const int* __restrict__ text)
{
    __shared__ __align__(16) float Bf[2][CPC][C];   // double-buffered gathered alpha
    __shared__ __align__(16) float part[4][CPC][CSL];
    __shared__ float red[CPC][CSL];
    __shared__ float inv_s[CPC];
    __shared__ float ls_s[CPC];
    __shared__ int toks[2][CPC];

    const int tid = threadIdx.x;
    const int rank = blockIdx.x & (CLU - 1);
    const int chain0 = (blockIdx.x >> 3) * CPC;
    const int c0 = rank * CSL;
    const int g = tid >> 6;      // K-group 0..3
    const int cl = tid & 63;     // local c'
    const int nn = tid >> 5;     // chain index in 128-thread phases
    const int jj = tid & 31;

    // P slice, packed along k: P2[k2] = {P[g*128+2k2][col], P[g*128+2k2+1][col]}
    unsigned long long P2[64];
#pragma unroll
    for (int k2 = 0; k2 < 64; ++k2) {
        float lo = g_P[(size_t)(g * 128 + 2 * k2) * C + c0 + cl];
        float hi = g_P[(size_t)(g * 128 + 2 * k2 + 1) * C + c0 + cl];
        P2[k2] = pk2(lo, hi);
    }

    if (tid < CPC) {
        toks[0][tid] = text[(chain0 + tid) * T + 0];
        toks[1][tid] = text[(chain0 + tid) * T + 1];
        ls_s[tid] = 0.f;
        inv_s[tid] = 1.f;
    }
    __syncthreads();

    // alpha0 into Bf[0] (each CTA computes the full replicated copy locally)
    for (int i = tid; i < CPC * C; i += 256) {
        int n = i >> 9, c = i & (C - 1);
        Bf[0][n][c] = g_startP[c] * g_emisT[(size_t)toks[0][n] * C + c];
    }
    __syncthreads();

    const unsigned bfAddr[2] = { smem_u32(&Bf[0][0][0]), smem_u32(&Bf[1][0][0]) };

    for (int t = 1; t < T; ++t) {
        const int rb = (t - 1) & 1, wb = t & 1;
        const bool resc = ((t & 3) == 1);

        // deferred rescale bookkeeping every 4 steps (on the read buffer)
        if (resc) {
            float mx = 0.f;
#pragma unroll
            for (int j = 0; j < 8; ++j) mx = fmaxf(mx, Bf[rb][g][cl + 64 * j]);
            red[g][cl] = mx;
            __syncthreads();
            if (tid < 128) {
                float v = fmaxf(red[nn][jj], red[nn][jj + 32]);
                v = warpMax(v);
                if (jj == 0) { inv_s[nn] = 1.f / v; ls_s[nn] += logf(v); }
            }
            __syncthreads();
        }

        // emission prefetch (token loaded during previous step)
        float ev0 = 0.f, ev1 = 0.f;
        if (tid < 128) {
            const float2 e2 = *(const float2*)(g_emisT +
                (size_t)toks[wb][nn] * C + c0 + 2 * jj);
            ev0 = e2.x; ev1 = e2.y;
        }
        if (tid >= 252 && t + 1 < T)
            toks[(t + 1) & 1][tid - 252] = text[(chain0 + tid - 252) * T + (t + 1)];

        // packed-FMA partial GEMV over this thread's 128-wide K-chunk, 4 chains
        unsigned long long a0 = 0ull, a1 = 0ull, a2 = 0ull, a3 = 0ull;
        {
            const ulonglong2* r0 = (const ulonglong2*)&Bf[rb][0][g * 128];
            const ulonglong2* r1 = (const ulonglong2*)&Bf[rb][1][g * 128];
            const ulonglong2* r2 = (const ulonglong2*)&Bf[rb][2][g * 128];
            const ulonglong2* r3 = (const ulonglong2*)&Bf[rb][3][g * 128];
#pragma unroll
            for (int k4 = 0; k4 < 32; ++k4) {
                const ulonglong2 v0 = r0[k4], v1 = r1[k4], v2 = r2[k4], v3 = r3[k4];
                const unsigned long long p0 = P2[2 * k4], p1 = P2[2 * k4 + 1];
                a0 = fma2(v0.x, p0, a0); a0 = fma2(v0.y, p1, a0);
                a1 = fma2(v1.x, p0, a1); a1 = fma2(v1.y, p1, a1);
                a2 = fma2(v2.x, p0, a2); a2 = fma2(v2.y, p1, a2);
                a3 = fma2(v3.x, p0, a3); a3 = fma2(v3.y, p1, a3);
            }
        }
        {
            float lo, hi;
            upk2(a0, lo, hi); part[g][0][cl] = lo + hi;
            upk2(a1, lo, hi); part[g][1][cl] = lo + hi;
            upk2(a2, lo, hi); part[g][2][cl] = lo + hi;
            upk2(a3, lo, hi); part[g][3][cl] = lo + hi;
        }
        __syncthreads();

        // reduce K-groups, apply emission (+inv on rescale steps), broadcast
        if (tid < 128) {
            const int cc = 2 * jj;
            const float inv = resc ? inv_s[nn] : 1.f;
            float s0 = ((part[0][nn][cc] + part[1][nn][cc]) +
                        (part[2][nn][cc] + part[3][nn][cc])) * (ev0 * inv);
            float s1 = ((part[0][nn][cc + 1] + part[1][nn][cc + 1]) +
                        (part[2][nn][cc + 1] + part[3][nn][cc + 1])) * (ev1 * inv);
            unsigned long long pk = pk2(s0, s1);
            unsigned base = bfAddr[wb] + (unsigned)((nn * C + c0 + cc) * 4);
#pragma unroll
            for (int r = 0; r < CLU; ++r) {
                unsigned ra;
                asm volatile("mapa.shared::cluster.u32 %0, %1, %2;"
                             : "=r"(ra) : "r"(base), "r"(r));
                asm volatile("st.shared::cluster.b64 [%0], %1;"
                             :: "r"(ra), "l"(pk) : "memory");
            }
        }
        asm volatile("barrier.cluster.arrive.aligned;" ::: "memory");
        asm volatile("barrier.cluster.wait.aligned;" ::: "memory");
    }

    // final: logZ[n] = ls[n] + log(sum_c Bf[last][n][c])
    {
        float sm = 0.f;
#pragma unroll
        for (int j = 0; j < 8; ++j) sm += Bf[(T - 1) & 1][g][cl + 64 * j];
        red[g][cl] = sm;
        __syncthreads();
        if (tid < 128) {
            float v = red[nn][jj] + red[nn][jj + 32];
            v = warpSum(v);
            if (jj == 0 && rank == 0)
                g_logZ[chain0 + nn] = ls_s[nn] + logf(v);
        }
    }
}

// ------------------------------ final reduction ------------------------------
__global__ void final_sum_kernel(float* __restrict__ out)
{
    __shared__ float s[64];
    int tid = threadIdx.x;
    s[tid] = g_logZ[tid];
    __syncthreads();
#pragma unroll
    for (int o = 32; o > 0; o >>= 1) {
        if (tid < o) s[tid] += s[tid + o];
        __syncthreads();
    }
    if (tid == 0) out[0] = s[0];
}

// ------------------------------ launch ------------------------------
extern "C" void kernel_launch(void* const* d_in, const int* in_sizes, int n_in,
                              void* d_out, int out_size)
{
    const int*   text  = (const int*)  d_in[0];
    const float* se    = (const float*)d_in[1];
    const float* sw    = (const float*)d_in[2];
    const float* sb    = (const float*)d_in[3];
    const float* srw   = (const float*)d_in[4];
    const float* srb   = (const float*)d_in[5];
    const float* state = (const float*)d_in[6];
    const float* nse   = (const float*)d_in[7];
    const float* pre   = (const float*)d_in[8];
    const float* trw   = (const float*)d_in[9];
    const float* trb   = (const float*)d_in[10];
    const float* term  = (const float*)d_in[11];
    float* out = (float*)d_out;

    start_kernel<<<1, 256>>>(se, sw, sb, srw, srb, nse);
    gemm_nt<<<dim3(C / GBN, C / GBM), 256>>>(state, nse, /*dest=*/0, C);
    p_softmax_kernel<<<C, 256>>>();
    term_mlp_kernel<<<C / TROWS, 256>>>(pre, trw, trb);
    gemm_nt<<<dim3(V / GBN, C / GBM), 256>>>(g_fe, term, /*dest=*/1, V);
    rowstats_kernel<<<C, 256>>>();
    norm_transpose_kernel<<<dim3(V / 32, C / 32), 256>>>();
    scan_kernel<<<(NB / CPC) * CLU, 256>>>(text);
    final_sum_kernel<<<1, 64>>>(out);
}